// round 15
// baseline (speedup 1.0000x reference)
#include <cuda_runtime.h>
#include <math.h>

#define NBATCH 64
#define NPTS   500
#define DIM    2048
#define KCL    10
#define NITER  10
#define EPSV   1e-6f
#define NSPLIT 2
#define NROWC  (NPTS / NSPLIT)   // 250
#define TILE   64                // 16 warps * 4 rows
#define NTILES 4
#define CHUNKF 128
#define NCHUNK (DIM / CHUNKF)    // 16
#define NBUF   4

// ---------------- persistent device scratch (parity double-buffered) --------
__device__ float g_part[2][NBATCH * NSPLIT][KCL * DIM];
__device__ int   g_pcnt[2][NBATCH * NSPLIT][KCL];
__device__ int   g_assign[NBATCH * NPTS];

// ---------------- helpers ----------------
__device__ __forceinline__ unsigned long long fma2(unsigned long long a,
                                                   unsigned long long b,
                                                   unsigned long long c) {
    unsigned long long d;
    asm("fma.rn.f32x2 %0, %1, %2, %3;" : "=l"(d) : "l"(a), "l"(b), "l"(c));
    return d;
}
__device__ __forceinline__ float2 unpack2(unsigned long long v) {
    float2 r;
    asm("mov.b64 {%0, %1}, %2;" : "=f"(r.x), "=f"(r.y) : "l"(v));
    return r;
}
__device__ __forceinline__ void cp16(unsigned int dst, const void* src) {
    asm volatile("cp.async.cg.shared.global [%0], [%1], 16;"
                 :: "r"(dst), "l"(src));
}
#define CP_COMMIT()  asm volatile("cp.async.commit_group;" ::: "memory")
#define CP_WAIT2()   asm volatile("cp.async.wait_group 2;"  ::: "memory")

// ---------------- init: parity-0 partials = first-K features ----------------
__global__ void init_kernel(const float* __restrict__ f) {
    int b = blockIdx.x / KCL, k = blockIdx.x % KCL;
    int d = threadIdx.x * 4;
    float4 z4 = make_float4(0.f, 0.f, 0.f, 0.f);
    float4 v = *(const float4*)(f + ((size_t)(b * NPTS + k)) * DIM + d);
    *(float4*)(&g_part[0][b * 2 + 0][k * DIM + d]) = v;
    *(float4*)(&g_part[0][b * 2 + 1][k * DIM + d]) = z4;
    if (threadIdx.x == 0) {
        g_pcnt[0][b * 2 + 0][k] = 1;
        g_pcnt[0][b * 2 + 1][k] = 0;
    }
}

// FMA block: same-acc updates spaced 4 apart
#define FMABLOCK(C0, C1, C2, C3)                                              \
    _Pragma("unroll")                                                         \
    for (int k = 0; k < KCL; k++) {                                           \
        ulonglong2 cc = *(const ulonglong2*)(scd + (size_t)k * DIM);          \
        acc[k][0] = fma2((C0).x, cc.x, acc[k][0]);                            \
        acc[k][1] = fma2((C1).x, cc.x, acc[k][1]);                            \
        acc[k][2] = fma2((C2).x, cc.x, acc[k][2]);                            \
        acc[k][3] = fma2((C3).x, cc.x, acc[k][3]);                            \
        acc[k][0] = fma2((C0).y, cc.y, acc[k][0]);                            \
        acc[k][1] = fma2((C1).y, cc.y, acc[k][1]);                            \
        acc[k][2] = fma2((C2).y, cc.y, acc[k][2]);                            \
        acc[k][3] = fma2((C3).y, cc.y, acc[k][3]);                            \
    }

// ---------------- fused iteration: per-warp pipelines, 1 barrier/tile ------
__global__ __launch_bounds__(512, 1) void iter_kernel(const float* __restrict__ feats,
                                                      int rd) {
    extern __shared__ float smem[];
    float* sc     = smem;                              // [KCL][DIM] 80KB
    float* fbuf   = smem + KCL * DIM;                  // [16][NBUF][4][CHUNKF] 128KB
    float* schalf = fbuf + 16 * NBUF * 4 * CHUNKF;     // [16]
    float* sinv   = schalf + 16;                       // [16]
    int*   sa2    = (int*)(sinv + 16);                 // [2][TILE]
    int*   spriv  = sa2 + 2 * TILE;                    // [16][TILE]
    int*   spoff  = spriv + 16 * TILE;                 // [16][12]
    int*   scnt   = spoff + 16 * 12;                   // [16]

    int bid = blockIdx.x;
    int b = bid >> 1, sp = bid & 1;
    int wr = rd ^ 1;
    int tid = threadIdx.x, warp = tid >> 5, lane = tid & 31;
    float4 z4 = make_float4(0.f, 0.f, 0.f, 0.f);

    unsigned int fba = (unsigned int)__cvta_generic_to_shared(fbuf)
                     + (unsigned int)(warp * NBUF * 4 * CHUNKF * 4);
    const float* frw = fbuf + (size_t)warp * NBUF * 4 * CHUNKF;
    int* myso = spriv + warp * TILE;
    int* mypo = spoff + warp * 12;

    const float* fb = feats + ((size_t)b * NPTS + (size_t)sp * NROWC) * DIM;
    int gabase = b * NPTS + sp * NROWC;
    int mywd = warp * 128 + lane * 4;

    // ---- tile-0 prologue FIRST: DRAM fetch starts before centroid reduce ---
    {
        int r0i = warp * 4;
        #pragma unroll
        for (int c = 0; c < 3; c++) {
            unsigned int dbase = fba + (unsigned int)(c * 4 * CHUNKF * 4);
            #pragma unroll
            for (int r = 0; r < 4; r++) {
                int g = min(r0i + r, NROWC - 1);
                cp16(dbase + (unsigned int)(r * CHUNKF * 4) + lane * 16,
                     (const char*)(fb + (size_t)g * DIM) + lane * 16
                     + c * (CHUNKF * 4));
            }
            CP_COMMIT();
        }
    }

    // ---- fused reduce: centroids = (part0 + part1) * inv -------------------
    if (tid < KCL) {
        int c = g_pcnt[rd][b * 2 + 0][tid] + g_pcnt[rd][b * 2 + 1][tid];
        sinv[tid] = 1.0f / (float)(c > 1 ? c : 1);
        scnt[tid] = 0;
    }
    __syncthreads();
    {
        const float4* q0 = (const float4*)g_part[rd][b * 2 + 0];
        const float4* q1 = (const float4*)g_part[rd][b * 2 + 1];
        for (int i = tid; i < KCL * DIM / 4; i += 512) {
            float4 a = q0[i], c = q1[i];
            float inv = sinv[i >> 9];
            ((float4*)sc)[i] = make_float4((a.x + c.x) * inv, (a.y + c.y) * inv,
                                           (a.z + c.z) * inv, (a.w + c.w) * inv);
        }
    }
    __syncthreads();

    if (warp < KCL) {
        float s = 0.f;
        for (int d = lane; d < DIM; d += 32) {
            float c = sc[warp * DIM + d];
            s = fmaf(c, c, s);
        }
        #pragma unroll
        for (int o = 16; o; o >>= 1) s += __shfl_xor_sync(0xffffffffu, s, o);
        if (lane == 0) schalf[warp] = 0.5f * s;
    }
    __syncthreads();

    for (int tile = 0; tile < NTILES; tile++) {
        int tbase = tile * TILE;
        int p = tile & 1;
        int* sa = sa2 + p * TILE;

        int r0i = tbase + warp * 4;
        const char* rp[4];
        #pragma unroll
        for (int r = 0; r < 4; r++) {
            int g = min(r0i + r, NROWC - 1);
            rp[r] = (const char*)(fb + (size_t)g * DIM) + lane * 16;
        }

        // ---------- phase A: per-warp pipelined FMA (no CTA barriers) -------
        unsigned long long acc[KCL][4];
        #pragma unroll
        for (int k = 0; k < KCL; k++)
            #pragma unroll
            for (int r = 0; r < 4; r++) acc[k][r] = 0ull;

        #pragma unroll 1
        for (int ch = 0; ch < NCHUNK; ch++) {
            CP_WAIT2();
            __syncwarp();

            const float* fr = frw + (size_t)(ch & 3) * (4 * CHUNKF) + lane * 4;
            ulonglong2 c0 = *(const ulonglong2*)(fr);
            ulonglong2 c1 = *(const ulonglong2*)(fr + CHUNKF);
            ulonglong2 c2 = *(const ulonglong2*)(fr + 2 * CHUNKF);
            ulonglong2 c3 = *(const ulonglong2*)(fr + 3 * CHUNKF);

            // issue next chunk's copies BEFORE the FMA block (prefetch dist ↑)
            if (ch < NCHUNK - 3) {
                int nc = ch + 3;
                unsigned int dbase = fba + (unsigned int)((nc & 3) * 4 * CHUNKF * 4);
                #pragma unroll
                for (int r = 0; r < 4; r++)
                    cp16(dbase + (unsigned int)(r * CHUNKF * 4) + lane * 16,
                         rp[r] + nc * (CHUNKF * 4));
            }
            CP_COMMIT();

            const float* scd = sc + ch * CHUNKF + lane * 4;
            FMABLOCK(c0, c1, c2, c3);
        }

        // ---------- issue NEXT tile's prologue now (ring fully drained) -----
        if (tile + 1 < NTILES) {
            int nb = tbase + TILE + warp * 4;
            #pragma unroll
            for (int c = 0; c < 3; c++) {
                unsigned int dbase = fba + (unsigned int)(c * 4 * CHUNKF * 4);
                #pragma unroll
                for (int r = 0; r < 4; r++) {
                    int g = min(nb + r, NROWC - 1);
                    const char* src = (const char*)(fb + (size_t)g * DIM)
                                    + lane * 16 + c * (CHUNKF * 4);
                    cp16(dbase + (unsigned int)(r * CHUNKF * 4) + lane * 16, src);
                }
                CP_COMMIT();
            }
        }

        // ---------- argmin ----------
        float dot[KCL][4];
        #pragma unroll
        for (int k = 0; k < KCL; k++) {
            #pragma unroll
            for (int r = 0; r < 4; r++) {
                float2 v = unpack2(acc[k][r]);
                float s = v.x + v.y;
                #pragma unroll
                for (int o = 16; o; o >>= 1)
                    s += __shfl_xor_sync(0xffffffffu, s, o);
                dot[k][r] = s;
            }
        }
        #pragma unroll
        for (int r = 0; r < 4; r++) {
            if (lane == r) {
                float best = schalf[0] - dot[0][r];
                int bi = 0;
                #pragma unroll
                for (int k = 1; k < KCL; k++) {
                    float s = schalf[k] - dot[k][r];
                    if (s < best) { best = s; bi = k; }
                }
                bool valid = (r0i + r) < NROWC;
                sa[warp * 4 + r] = valid ? bi : -1;
                if (valid) g_assign[gabase + r0i + r] = bi;
            }
        }
        __syncthreads();   // the ONLY barrier per tile

        // ---------- redundant per-warp counting sort (uniform shuffles) -----
        {
            int a0 = sa[lane];
            int a1 = sa[32 + lane];
            int cnt0 = 0, cnttot = 0;
            unsigned bal0 = 0, bal1 = 0;
            #pragma unroll
            for (int k = 0; k < KCL; k++) {
                unsigned m0 = __ballot_sync(0xffffffffu, a0 == k);
                unsigned m1 = __ballot_sync(0xffffffffu, a1 == k);
                if (lane == k) { cnt0 = __popc(m0); cnttot = __popc(m0) + __popc(m1); }
                if (a0 == k) bal0 = m0;
                if (a1 == k) bal1 = m1;
            }
            int v = cnttot;
            #pragma unroll
            for (int o = 1; o < 16; o <<= 1) {
                int t = __shfl_up_sync(0xffffffffu, v, o);
                if (lane >= o) v += t;
            }
            int excl = v - cnttot;
            if (lane < KCL) mypo[lane] = excl;
            if (lane == KCL - 1) mypo[KCL] = v;
            if (warp == 0 && lane < KCL) scnt[lane] += cnttot;

            int ia0 = (a0 >= 0) ? a0 : 0;
            int ia1 = (a1 >= 0) ? a1 : 0;
            int off0  = __shfl_sync(0xffffffffu, excl, ia0);
            int exc1  = __shfl_sync(0xffffffffu, excl, ia1);
            int cntp0 = __shfl_sync(0xffffffffu, cnt0, ia1);
            if (a0 >= 0) {
                int rank = __popc(bal0 & ((1u << lane) - 1u));
                myso[off0 + rank] = lane;
            }
            if (a1 >= 0) {
                int rank = __popc(bal1 & ((1u << lane) - 1u));
                myso[exc1 + cntp0 + rank] = 32 + lane;
            }
            __syncwarp();
        }

        // ---------- phase B: private sorted lists -> g_part (store/RMW) -----
        {
            const float* fsl = fb + (size_t)tbase * DIM + mywd;
            float* gslice = &g_part[wr][bid][mywd];
            #pragma unroll
            for (int k = 0; k < KCL; k++) {
                int s0 = mypo[k], s1 = mypo[k + 1];
                float* gp = gslice + (size_t)k * DIM;
                float4 a4 = z4, b4 = z4;
                if (s0 != s1) {
                    int idx = s0;
                    for (; idx + 2 <= s1; idx += 2) {
                        int na = myso[idx], nb = myso[idx + 1];
                        float4 fa = *(const float4*)(fsl + (size_t)na * DIM);
                        float4 fc = *(const float4*)(fsl + (size_t)nb * DIM);
                        a4.x += fa.x; a4.y += fa.y; a4.z += fa.z; a4.w += fa.w;
                        b4.x += fc.x; b4.y += fc.y; b4.z += fc.z; b4.w += fc.w;
                    }
                    if (idx < s1) {
                        int na = myso[idx];
                        float4 fa = *(const float4*)(fsl + (size_t)na * DIM);
                        a4.x += fa.x; a4.y += fa.y; a4.z += fa.z; a4.w += fa.w;
                    }
                }
                float4 o0;
                if (tile == 0) {
                    o0 = make_float4(a4.x + b4.x, a4.y + b4.y,
                                     a4.z + b4.z, a4.w + b4.w);
                } else {
                    if (s0 == s1) continue;
                    o0 = *(const float4*)gp;
                    o0.x += a4.x + b4.x; o0.y += a4.y + b4.y;
                    o0.z += a4.z + b4.z; o0.w += a4.w + b4.w;
                }
                *(float4*)gp = o0;
            }
        }
        // no trailing barrier: sa double-buffered, phase-B state warp-private
    }

    __syncthreads();
    if (tid < KCL) g_pcnt[wr][bid][tid] = scnt[tid];
}

// ---------------- final GeM pooling: streaming, one pass --------------------
__device__ __forceinline__ void gem_sel(float2* bacc, int* bcnt, int a, float2 f) {
    float x = fmaxf(f.x, EPSV), y = fmaxf(f.y, EPSV);
    float px = x * x * x, py = y * y * y;
    switch (a) {
#define GCASE(K) case K: bacc[K].x += px; bacc[K].y += py; bcnt[K]++; break;
        GCASE(0) GCASE(1) GCASE(2) GCASE(3) GCASE(4)
        GCASE(5) GCASE(6) GCASE(7) GCASE(8) GCASE(9)
#undef GCASE
        default: break;
    }
}
__device__ __forceinline__ void gem_sel_p(float2* bacc, int* bcnt, int a,
                                          float2 f, float pv) {
    float px = powf(fmaxf(f.x, EPSV), pv), py = powf(fmaxf(f.y, EPSV), pv);
    switch (a) {
#define GCASE(K) case K: bacc[K].x += px; bacc[K].y += py; bcnt[K]++; break;
        GCASE(0) GCASE(1) GCASE(2) GCASE(3) GCASE(4)
        GCASE(5) GCASE(6) GCASE(7) GCASE(8) GCASE(9)
#undef GCASE
        default: break;
    }
}

__global__ __launch_bounds__(512) void final_kernel(const float* __restrict__ feats,
                                                    const float* __restrict__ pp,
                                                    float* __restrict__ out) {
    __shared__ int sa[NPTS];
    int b = blockIdx.x >> 1, h = blockIdx.x & 1;
    int tid = threadIdx.x;
    for (int i = tid; i < NPTS; i += 512) sa[i] = g_assign[b * NPTS + i];
    __syncthreads();

    float pv = pp[0];
    bool p3 = (pv == 3.0f);
    int dbase = h * (DIM / 2) + tid * 2;
    const float* fb = feats + (size_t)b * NPTS * DIM + dbase;

    float2 bacc[KCL];
    int bcnt[KCL];
    #pragma unroll
    for (int k = 0; k < KCL; k++) { bacc[k] = make_float2(0.f, 0.f); bcnt[k] = 0; }

    if (p3) {
        #pragma unroll 1
        for (int n = 0; n < NPTS; n += 4) {
            float2 f0 = *(const float2*)(fb + (size_t)(n + 0) * DIM);
            float2 f1 = *(const float2*)(fb + (size_t)(n + 1) * DIM);
            float2 f2 = *(const float2*)(fb + (size_t)(n + 2) * DIM);
            float2 f3 = *(const float2*)(fb + (size_t)(n + 3) * DIM);
            int a0 = sa[n], a1 = sa[n + 1], a2 = sa[n + 2], a3 = sa[n + 3];
            gem_sel(bacc, bcnt, a0, f0);
            gem_sel(bacc, bcnt, a1, f1);
            gem_sel(bacc, bcnt, a2, f2);
            gem_sel(bacc, bcnt, a3, f3);
        }
    } else {
        #pragma unroll 1
        for (int n = 0; n < NPTS; n++) {
            float2 f0 = *(const float2*)(fb + (size_t)n * DIM);
            gem_sel_p(bacc, bcnt, sa[n], f0, pv);
        }
    }

    size_t obase = (size_t)b * KCL * DIM + dbase;
    float ip = 1.0f / pv;
    #pragma unroll
    for (int k = 0; k < KCL; k++) {
        float2 o;
        if (bcnt[k] > 0) {
            float inv = 1.0f / (float)bcnt[k];
            if (p3) {
                o.x = cbrtf(bacc[k].x * inv);
                o.y = cbrtf(bacc[k].y * inv);
            } else {
                o.x = powf(bacc[k].x * inv, ip);
                o.y = powf(bacc[k].y * inv, ip);
            }
        } else {
            o = make_float2(0.f, 0.f);
        }
        *(float2*)(out + obase + (size_t)k * DIM) = o;
    }
}

// ---------------- launch ----------------
extern "C" void kernel_launch(void* const* d_in, const int* in_sizes, int n_in,
                              void* d_out, int out_size) {
    const float* feats = (const float*)d_in[0];
    const float* p     = (const float*)d_in[1];
    float* out         = (float*)d_out;

    const int smem_iter = (KCL * DIM + 16 * NBUF * 4 * CHUNKF + 32) * sizeof(float)
                        + (2 * TILE + 16 * TILE + 16 * 12 + 16) * sizeof(int);
    cudaFuncSetAttribute(iter_kernel,
                         cudaFuncAttributeMaxDynamicSharedMemorySize, smem_iter);

    init_kernel<<<NBATCH * KCL, 512>>>(feats);
    for (int it = 0; it < NITER; it++)
        iter_kernel<<<NBATCH * NSPLIT, 512, smem_iter>>>(feats, it & 1);
    final_kernel<<<NBATCH * 2, 512>>>(feats, p, out);
}

// round 16
// speedup vs baseline: 1.0601x; 1.0601x over previous
#include <cuda_runtime.h>
#include <math.h>

#define NBATCH 64
#define NPTS   500
#define DIM    2048
#define KCL    10
#define NITER  10
#define EPSV   1e-6f
#define NSPLIT 2
#define NROWC  (NPTS / NSPLIT)   // 250
#define TILE   64                // 16 warps * 4 rows
#define NTILES 4
#define CHUNKF 128
#define NCHUNK (DIM / CHUNKF)    // 16
#define NBUF   4                 // per-warp ring depth

// ---------------- persistent device scratch (parity double-buffered) --------
__device__ float g_part[2][NBATCH * NSPLIT][KCL * DIM];
__device__ int   g_pcnt[2][NBATCH * NSPLIT][KCL];
__device__ int   g_assign[NBATCH * NPTS];

// ---------------- helpers ----------------
__device__ __forceinline__ unsigned long long fma2(unsigned long long a,
                                                   unsigned long long b,
                                                   unsigned long long c) {
    unsigned long long d;
    asm("fma.rn.f32x2 %0, %1, %2, %3;" : "=l"(d) : "l"(a), "l"(b), "l"(c));
    return d;
}
__device__ __forceinline__ float2 unpack2(unsigned long long v) {
    float2 r;
    asm("mov.b64 {%0, %1}, %2;" : "=f"(r.x), "=f"(r.y) : "l"(v));
    return r;
}
__device__ __forceinline__ void cp16(unsigned int dst, const void* src) {
    asm volatile("cp.async.cg.shared.global [%0], [%1], 16;"
                 :: "r"(dst), "l"(src));
}
#define CP_COMMIT()  asm volatile("cp.async.commit_group;" ::: "memory")
#define CP_WAIT2()   asm volatile("cp.async.wait_group 2;"  ::: "memory")

// ---------------- init: parity-0 partials = first-K features ----------------
__global__ void init_kernel(const float* __restrict__ f) {
    int b = blockIdx.x / KCL, k = blockIdx.x % KCL;
    int d = threadIdx.x * 4;
    float4 z4 = make_float4(0.f, 0.f, 0.f, 0.f);
    float4 v = *(const float4*)(f + ((size_t)(b * NPTS + k)) * DIM + d);
    *(float4*)(&g_part[0][b * 2 + 0][k * DIM + d]) = v;
    *(float4*)(&g_part[0][b * 2 + 1][k * DIM + d]) = z4;
    if (threadIdx.x == 0) {
        g_pcnt[0][b * 2 + 0][k] = 1;
        g_pcnt[0][b * 2 + 1][k] = 0;
    }
}

// FMA block: same-acc updates spaced 4 apart
#define FMABLOCK(C0, C1, C2, C3)                                              \
    _Pragma("unroll")                                                         \
    for (int k = 0; k < KCL; k++) {                                           \
        ulonglong2 cc = *(const ulonglong2*)(scd + (size_t)k * DIM);          \
        acc[k][0] = fma2((C0).x, cc.x, acc[k][0]);                            \
        acc[k][1] = fma2((C1).x, cc.x, acc[k][1]);                            \
        acc[k][2] = fma2((C2).x, cc.x, acc[k][2]);                            \
        acc[k][3] = fma2((C3).x, cc.x, acc[k][3]);                            \
        acc[k][0] = fma2((C0).y, cc.y, acc[k][0]);                            \
        acc[k][1] = fma2((C1).y, cc.y, acc[k][1]);                            \
        acc[k][2] = fma2((C2).y, cc.y, acc[k][2]);                            \
        acc[k][3] = fma2((C3).y, cc.y, acc[k][3]);                            \
    }

// ---------------- fused iteration (R11 structure, measured 105.3us) --------
// grid = 128 (b, sp), block = 512, ~209KB smem, 1 CTA/SM.
__global__ __launch_bounds__(512, 1) void iter_kernel(const float* __restrict__ feats,
                                                      int rd) {
    extern __shared__ float smem[];
    float* sc     = smem;                              // [KCL][DIM] 80KB
    float* fbuf   = smem + KCL * DIM;                  // [16][NBUF][4][CHUNKF] 128KB
    float* schalf = fbuf + 16 * NBUF * 4 * CHUNKF;     // [16]
    float* sinv   = schalf + 16;                       // [16]
    int*   sa      = (int*)(sinv + 16);                // [TILE]
    int*   ssorted = sa + TILE;                        // [TILE]
    int*   soff    = ssorted + TILE;                   // [12]
    int*   srun    = soff + 12;                        // [10]
    int*   scnt    = srun + 10;                        // [16]

    int bid = blockIdx.x;
    int b = bid >> 1, sp = bid & 1;
    int wr = rd ^ 1;
    int tid = threadIdx.x, warp = tid >> 5, lane = tid & 31;
    float4 z4 = make_float4(0.f, 0.f, 0.f, 0.f);

    unsigned int fba = (unsigned int)__cvta_generic_to_shared(fbuf)
                     + (unsigned int)(warp * NBUF * 4 * CHUNKF * 4);
    const float* frw = fbuf + (size_t)warp * NBUF * 4 * CHUNKF;

    // ---- fused reduce: centroids = (part0 + part1) * inv; zero wr slot -----
    if (tid < KCL) {
        int c = g_pcnt[rd][b * 2 + 0][tid] + g_pcnt[rd][b * 2 + 1][tid];
        sinv[tid] = 1.0f / (float)(c > 1 ? c : 1);
        scnt[tid] = 0;
    }
    __syncthreads();
    {
        const float4* q0 = (const float4*)g_part[rd][b * 2 + 0];
        const float4* q1 = (const float4*)g_part[rd][b * 2 + 1];
        float4* zw = (float4*)g_part[wr][bid];
        for (int i = tid; i < KCL * DIM / 4; i += 512) {
            float4 a = q0[i], c = q1[i];
            float inv = sinv[i >> 9];
            ((float4*)sc)[i] = make_float4((a.x + c.x) * inv, (a.y + c.y) * inv,
                                           (a.z + c.z) * inv, (a.w + c.w) * inv);
            zw[i] = z4;
        }
    }
    __syncthreads();

    if (warp < KCL) {
        float s = 0.f;
        for (int d = lane; d < DIM; d += 32) {
            float c = sc[warp * DIM + d];
            s = fmaf(c, c, s);
        }
        #pragma unroll
        for (int o = 16; o; o >>= 1) s += __shfl_xor_sync(0xffffffffu, s, o);
        if (lane == 0) schalf[warp] = 0.5f * s;
    }
    __syncthreads();

    const float* fb = feats + ((size_t)b * NPTS + (size_t)sp * NROWC) * DIM;
    int gabase = b * NPTS + sp * NROWC;
    int mywd = warp * 128 + lane * 4;

    for (int tile = 0; tile < NTILES; tile++) {
        int tbase = tile * TILE;
        int nrows = NROWC - tbase; if (nrows > TILE) nrows = TILE;

        // warp's 4 rows (clamped)
        int r0i = tbase + warp * 4;
        const char* rp[4];
        #pragma unroll
        for (int r = 0; r < 4; r++) {
            int g = min(r0i + r, NROWC - 1);
            rp[r] = (const char*)(fb + (size_t)g * DIM) + lane * 16;
        }

        // ---------- prologue: issue chunks 0..2 into ring bufs 0..2 --------
        #pragma unroll
        for (int c = 0; c < 3; c++) {
            unsigned int dbase = fba + (unsigned int)(c * 4 * CHUNKF * 4);
            #pragma unroll
            for (int r = 0; r < 4; r++)
                cp16(dbase + (unsigned int)(r * CHUNKF * 4) + lane * 16,
                     rp[r] + c * (CHUNKF * 4));
            CP_COMMIT();
        }

        // ---------- phase A: per-warp pipelined FMA (no CTA barriers) -------
        unsigned long long acc[KCL][4];
        #pragma unroll
        for (int k = 0; k < KCL; k++)
            #pragma unroll
            for (int r = 0; r < 4; r++) acc[k][r] = 0ull;

        #pragma unroll 1
        for (int ch = 0; ch < NCHUNK; ch++) {
            CP_WAIT2();
            __syncwarp();

            const float* fr = frw + (size_t)(ch & 3) * (4 * CHUNKF) + lane * 4;
            ulonglong2 c0 = *(const ulonglong2*)(fr);
            ulonglong2 c1 = *(const ulonglong2*)(fr + CHUNKF);
            ulonglong2 c2 = *(const ulonglong2*)(fr + 2 * CHUNKF);
            ulonglong2 c3 = *(const ulonglong2*)(fr + 3 * CHUNKF);
            const float* scd = sc + ch * CHUNKF + lane * 4;
            FMABLOCK(c0, c1, c2, c3);

            if (ch < NCHUNK - 3) {
                int nc = ch + 3;
                unsigned int dbase = fba + (unsigned int)((nc & 3) * 4 * CHUNKF * 4);
                #pragma unroll
                for (int r = 0; r < 4; r++)
                    cp16(dbase + (unsigned int)(r * CHUNKF * 4) + lane * 16,
                         rp[r] + nc * (CHUNKF * 4));
            }
            CP_COMMIT();
        }

        // reduce + argmin
        float dot[KCL][4];
        #pragma unroll
        for (int k = 0; k < KCL; k++) {
            #pragma unroll
            for (int r = 0; r < 4; r++) {
                float2 v = unpack2(acc[k][r]);
                float s = v.x + v.y;
                #pragma unroll
                for (int o = 16; o; o >>= 1)
                    s += __shfl_xor_sync(0xffffffffu, s, o);
                dot[k][r] = s;
            }
        }
        #pragma unroll
        for (int r = 0; r < 4; r++) {
            if (lane == r) {
                float best = schalf[0] - dot[0][r];
                int bi = 0;
                #pragma unroll
                for (int k = 1; k < KCL; k++) {
                    float s = schalf[k] - dot[k][r];
                    if (s < best) { best = s; bi = k; }
                }
                bool valid = (r0i + r) < NROWC;
                sa[warp * 4 + r] = valid ? bi : -1;
                if (valid) g_assign[gabase + r0i + r] = bi;
            }
        }
        __syncthreads();   // sa complete

        // ---------- counting sort (warp 0, two 32-wide passes) ----------
        if (warp == 0) {
            int mycnt = 0;
            #pragma unroll
            for (int q = 0; q < 2; q++) {
                int n = q * 32 + lane;
                int a = (n < nrows) ? sa[n] : -1;
                #pragma unroll
                for (int k = 0; k < KCL; k++) {
                    unsigned m = __ballot_sync(0xffffffffu, a == k);
                    if (lane == k) mycnt += __popc(m);
                }
            }
            int v = (lane < KCL) ? mycnt : 0;
            #pragma unroll
            for (int o = 1; o < 16; o <<= 1) {
                int t = __shfl_up_sync(0xffffffffu, v, o);
                if (lane >= o) v += t;
            }
            int excl = v - ((lane < KCL) ? mycnt : 0);
            if (lane < KCL) { soff[lane] = excl; srun[lane] = excl; scnt[lane] += mycnt; }
            if (lane == KCL - 1) soff[KCL] = v;
            __syncwarp();
            #pragma unroll
            for (int q = 0; q < 2; q++) {
                int n = q * 32 + lane;
                int a = (n < nrows) ? sa[n] : -1;
                unsigned mybal = 0;
                #pragma unroll
                for (int k = 0; k < KCL; k++) {
                    unsigned m = __ballot_sync(0xffffffffu, a == k);
                    if (a == k) mybal = m;
                }
                if (a >= 0) {
                    int rank = __popc(mybal & ((1u << lane) - 1u));
                    ssorted[srun[a] + rank] = n;
                    if (rank == __popc(mybal) - 1) srun[a] += rank + 1;
                }
                __syncwarp();
            }
        }
        __syncthreads();

        // ---------- phase B: sorted lists -> register sums -> g_part RMW ----
        {
            const float* fsl = fb + (size_t)tbase * DIM + mywd;
            float* gslice = &g_part[wr][bid][mywd];
            #pragma unroll
            for (int k = 0; k < KCL; k++) {
                int s0 = soff[k], s1 = soff[k + 1];
                if (s0 == s1) continue;
                float* gp = gslice + (size_t)k * DIM;
                float4 o0 = *(const float4*)gp;
                float4 a4 = z4, b4 = z4;
                int idx = s0;
                for (; idx + 2 <= s1; idx += 2) {
                    int na = ssorted[idx], nb = ssorted[idx + 1];
                    float4 fa = *(const float4*)(fsl + (size_t)na * DIM);
                    float4 fc = *(const float4*)(fsl + (size_t)nb * DIM);
                    a4.x += fa.x; a4.y += fa.y; a4.z += fa.z; a4.w += fa.w;
                    b4.x += fc.x; b4.y += fc.y; b4.z += fc.z; b4.w += fc.w;
                }
                if (idx < s1) {
                    int na = ssorted[idx];
                    float4 fa = *(const float4*)(fsl + (size_t)na * DIM);
                    a4.x += fa.x; a4.y += fa.y; a4.z += fa.z; a4.w += fa.w;
                }
                o0.x += a4.x + b4.x; o0.y += a4.y + b4.y;
                o0.z += a4.z + b4.z; o0.w += a4.w + b4.w;
                *(float4*)gp = o0;
            }
        }
        // no trailing barrier: next tile's sa-barrier provides ordering
    }

    __syncthreads();
    if (tid < KCL) g_pcnt[wr][bid][tid] = scnt[tid];
}

// ---------------- final GeM pooling: streaming, one pass (R14) --------------
__device__ __forceinline__ void gem_sel(float2* bacc, int* bcnt, int a, float2 f) {
    float x = fmaxf(f.x, EPSV), y = fmaxf(f.y, EPSV);
    float px = x * x * x, py = y * y * y;
    switch (a) {
#define GCASE(K) case K: bacc[K].x += px; bacc[K].y += py; bcnt[K]++; break;
        GCASE(0) GCASE(1) GCASE(2) GCASE(3) GCASE(4)
        GCASE(5) GCASE(6) GCASE(7) GCASE(8) GCASE(9)
#undef GCASE
        default: break;
    }
}
__device__ __forceinline__ void gem_sel_p(float2* bacc, int* bcnt, int a,
                                          float2 f, float pv) {
    float px = powf(fmaxf(f.x, EPSV), pv), py = powf(fmaxf(f.y, EPSV), pv);
    switch (a) {
#define GCASE(K) case K: bacc[K].x += px; bacc[K].y += py; bcnt[K]++; break;
        GCASE(0) GCASE(1) GCASE(2) GCASE(3) GCASE(4)
        GCASE(5) GCASE(6) GCASE(7) GCASE(8) GCASE(9)
#undef GCASE
        default: break;
    }
}

__global__ __launch_bounds__(512) void final_kernel(const float* __restrict__ feats,
                                                    const float* __restrict__ pp,
                                                    float* __restrict__ out) {
    __shared__ int sa[NPTS];
    int b = blockIdx.x >> 1, h = blockIdx.x & 1;
    int tid = threadIdx.x;
    for (int i = tid; i < NPTS; i += 512) sa[i] = g_assign[b * NPTS + i];
    __syncthreads();

    float pv = pp[0];
    bool p3 = (pv == 3.0f);
    int dbase = h * (DIM / 2) + tid * 2;
    const float* fb = feats + (size_t)b * NPTS * DIM + dbase;

    float2 bacc[KCL];
    int bcnt[KCL];
    #pragma unroll
    for (int k = 0; k < KCL; k++) { bacc[k] = make_float2(0.f, 0.f); bcnt[k] = 0; }

    if (p3) {
        #pragma unroll 1
        for (int n = 0; n < NPTS; n += 4) {
            float2 f0 = *(const float2*)(fb + (size_t)(n + 0) * DIM);
            float2 f1 = *(const float2*)(fb + (size_t)(n + 1) * DIM);
            float2 f2 = *(const float2*)(fb + (size_t)(n + 2) * DIM);
            float2 f3 = *(const float2*)(fb + (size_t)(n + 3) * DIM);
            int a0 = sa[n], a1 = sa[n + 1], a2 = sa[n + 2], a3 = sa[n + 3];
            gem_sel(bacc, bcnt, a0, f0);
            gem_sel(bacc, bcnt, a1, f1);
            gem_sel(bacc, bcnt, a2, f2);
            gem_sel(bacc, bcnt, a3, f3);
        }
    } else {
        #pragma unroll 1
        for (int n = 0; n < NPTS; n++) {
            float2 f0 = *(const float2*)(fb + (size_t)n * DIM);
            gem_sel_p(bacc, bcnt, sa[n], f0, pv);
        }
    }

    size_t obase = (size_t)b * KCL * DIM + dbase;
    float ip = 1.0f / pv;
    #pragma unroll
    for (int k = 0; k < KCL; k++) {
        float2 o;
        if (bcnt[k] > 0) {
            float inv = 1.0f / (float)bcnt[k];
            if (p3) {
                o.x = cbrtf(bacc[k].x * inv);
                o.y = cbrtf(bacc[k].y * inv);
            } else {
                o.x = powf(bacc[k].x * inv, ip);
                o.y = powf(bacc[k].y * inv, ip);
            }
        } else {
            o = make_float2(0.f, 0.f);
        }
        *(float2*)(out + obase + (size_t)k * DIM) = o;
    }
}

// ---------------- launch ----------------
extern "C" void kernel_launch(void* const* d_in, const int* in_sizes, int n_in,
                              void* d_out, int out_size) {
    const float* feats = (const float*)d_in[0];
    const float* p     = (const float*)d_in[1];
    float* out         = (float*)d_out;

    const int smem_iter = (KCL * DIM + 16 * NBUF * 4 * CHUNKF + 32) * sizeof(float)
                        + (TILE + TILE + 12 + 10 + 16) * sizeof(int);
    cudaFuncSetAttribute(iter_kernel,
                         cudaFuncAttributeMaxDynamicSharedMemorySize, smem_iter);

    init_kernel<<<NBATCH * KCL, 512>>>(feats);
    for (int it = 0; it < NITER; it++)
        iter_kernel<<<NBATCH * NSPLIT, 512, smem_iter>>>(feats, it & 1);
    final_kernel<<<NBATCH * 2, 512>>>(feats, p, out);
}